// round 10
// baseline (speedup 1.0000x reference)
#include <cuda_runtime.h>
#include <math.h>
#include <stdint.h>

// Problem constants
#define BB 512
#define NN 64
#define EE 512
#define AA 16
#define ITERS 8
#define TPB 512          // threads per CTA (one CTA per batch)
#define EINV (1.0f / 512.0f)

// Adjacency (CSR, ascending edge order) -- built once per launch on device.
__device__ int g_to_off[NN + 1], g_from_off[NN + 1];
__device__ int g_to_lst[EE], g_from_lst[EE];

__global__ void build_adj_kernel(const int* __restrict__ ef, const int* __restrict__ et) {
    __shared__ int sf[EE], st[EE];
    __shared__ int cto[NN], cfr[NN];
    int t = threadIdx.x;
    for (int e = t; e < EE; e += blockDim.x) { sf[e] = ef[e]; st[e] = et[e]; }
    __syncthreads();
    if (t < NN) {
        int ct = 0, cf = 0;
        for (int e = 0; e < EE; e++) { ct += (st[e] == t); cf += (sf[e] == t); }
        cto[t] = ct; cfr[t] = cf;
    }
    __syncthreads();
    if (t == 0) {
        int a = 0, b = 0;
        for (int n = 0; n < NN; n++) {
            g_to_off[n] = a; a += cto[n];
            g_from_off[n] = b; b += cfr[n];
        }
        g_to_off[NN] = a; g_from_off[NN] = b;
    }
    __syncthreads();
    if (t < NN) {
        int ot = g_to_off[t], of = g_from_off[t];
        for (int e = 0; e < EE; e++) {
            if (st[e] == t) g_to_lst[ot++] = e;
            if (sf[e] == t) g_from_lst[of++] = e;
        }
    }
}

// SMEM layout (floats):
//  q0:1024  q:1024  mf:8192  mb:8192
//  red:16 red_node:2 qmax:1  ints: a_cur:64 a_best:64 flag:1 ef:512 et:512
#define SMEM_WORDS (1024 + 1024 + 8192 + 8192 + 16 + 2 + 1 + 64 + 64 + 1 + 512 + 512)
#define SMEM_BYTES (SMEM_WORDS * 4)    // ~76.6KB -> 2 CTAs per SM

__device__ __forceinline__ float4 f4_sub(float4 a, float4 b) {
    float4 r;
    r.x = a.x - b.x; r.y = a.y - b.y; r.z = a.z - b.z; r.w = a.w - b.w;
    return r;
}
// max over 4 elements of (T*EINV + u[j])  -- exact: T*EINV product exact,
// single rounding per add, fmax exactly associative.
__device__ __forceinline__ float seg_max(float4 T, float4 u) {
    float a = fmaxf(fmaf(T.x, EINV, u.x), fmaf(T.y, EINV, u.y));
    float b = fmaxf(fmaf(T.z, EINV, u.z), fmaf(T.w, EINV, u.w));
    return fmaxf(a, b);
}

__global__ __launch_bounds__(TPB, 2)
void dcg_kernel(const float* __restrict__ nodev, const float* __restrict__ edgev,
                const int* __restrict__ ef, const int* __restrict__ et,
                float* __restrict__ out)
{
    extern __shared__ float smem[];
    float* q0      = smem;                        // 1024
    float* q       = q0 + 1024;                   // 1024
    float* mf      = q + 1024;                    // 8192
    float* mb      = mf + 8192;                   // 8192
    float* red     = mb + 8192;                   // 16
    float* red_node = red + 16;                   // 2
    float* qmax_s  = red_node + 2;                // 1
    int* a_cur  = (int*)(qmax_s + 1);             // 64
    int* a_best = a_cur + 64;                     // 64
    int* flag   = a_best + 64;                    // 1
    int* ef_s   = flag + 1;                       // 512
    int* et_s   = ef_s + EE;                      // 512

    const int tid    = threadIdx.x;
    const int b      = blockIdx.x;
    const int halfid = tid >> 4;        // 0..31 half-warp id
    const int hl     = tid & 15;        // lane within half-warp
    const int sseg   = hl & 3;          // column segment (s)
    const int kgrp   = hl >> 2;         // row-group offset (k)
    const unsigned hmask = 0xFFFFu << ((halfid & 1) * 16);
    const int warp = tid >> 5;
    const int lane = tid & 31;

    const float* nb    = nodev + (size_t)b * NN * AA;
    const float* ebase = edgev + (size_t)b * EE * AA * AA;

    // ---- init
    for (int i = tid; i < NN * AA; i += TPB) {
        float v = nb[i] * 0.015625f;   // /64 exact
        q0[i] = v; q[i] = v;
    }
    for (int i = tid; i < EE * AA; i += TPB) { mf[i] = 0.f; mb[i] = 0.f; }
    for (int i = tid; i < EE; i += TPB) { ef_s[i] = ef[i]; et_s[i] = et[i]; }
    __syncthreads();

    // ---- argmax of q-array per node (lowest index wins ties, like jnp.argmax)
    auto do_argmax = [&](const float* qa) {
        for (int n = halfid; n < NN; n += 32) {
            float bv = qa[n * AA + hl]; int bi = hl;
            #pragma unroll
            for (int o = 8; o; o >>= 1) {
                float ov = __shfl_xor_sync(hmask, bv, o, 16);
                int   oi = __shfl_xor_sync(hmask, bi, o, 16);
                if (ov > bv || (ov == bv && oi < bi)) { bv = ov; bi = oi; }
            }
            if (hl == 0) a_cur[n] = bi;
        }
    };

    // ---- evaluate action a_cur, update (q_max, a_best). Caller syncs before.
    auto do_eval = [&](bool first) {
        float ev;
        {
            int e  = tid;
            int af = a_cur[ef_s[e]];
            int at = a_cur[et_s[e]];
            ev = ebase[(size_t)e * 256 + af * 16 + at];
        }
        #pragma unroll
        for (int o = 16; o; o >>= 1) ev += __shfl_xor_sync(0xffffffffu, ev, o, 32);
        if (lane == 0) red[warp] = ev;
        if (tid < NN) {
            float nv = q0[tid * AA + a_cur[tid]] * 64.0f;   // node_vals exact
            #pragma unroll
            for (int o = 16; o; o >>= 1) nv += __shfl_xor_sync(0xffffffffu, nv, o, 32);
            if (lane == 0) red_node[warp] = nv;
        }
        __syncthreads();
        if (tid == 0) {
            float es = 0.f;
            #pragma unroll
            for (int w = 0; w < 16; w++) es += red[w];
            float ns = red_node[0] + red_node[1];
            float qv = ns * (1.0f / 64.0f) + es * (1.0f / 512.0f);
            if (first || qv > *qmax_s) { *qmax_s = qv; *flag = 1; }
            else *flag = 0;
        }
        __syncthreads();
        if (*flag && tid < NN) a_best[tid] = a_cur[tid];
        __syncthreads();
    };

    // ---- initial: a_max = argmax(node_vals), q_max = eval
    do_argmax(q0);
    __syncthreads();
    do_eval(true);

    // ---- message-passing iterations
    for (int it = 0; it < ITERS; it++) {
        // Phase 1: one edge per half-warp per pass, coalesced chunk-ownership:
        // 4 coalesced LDG.128 -> lane hl (= 4k+s) holds rows {4i+k}, columns
        // [4s..4s+3] of the tile. mb via seg-partials + offset{1,2} butterfly;
        // mf via row-partials + offset{4,8} butterfly. All maxes are exact
        // reassociations of the reference max; means are bitwise-uniform per
        // edge (commutative butterflies) -> argmax-safe.
        for (int pass = 0; pass < 16; ++pass) {
            const int e = halfid + 32 * pass;
            const int nf = ef_s[e], nt = et_s[e];

            // ---- hoisted loads of ALL old state (before any store this pass)
            // ub segment (4 cols 4s..4s+3), broadcast within group:
            const float4 qnt4 = *(const float4*)(q  + nt * AA + 4 * sseg);
            const float4 mfo4 = *(const float4*)(mf + e  * AA + 4 * sseg);
            const float4 ubv  = f4_sub(qnt4, mfo4);
            // uf scalars for rows 4i+k:
            float uf0 = q[nf * AA + 0  + kgrp] - mb[e * AA + 0  + kgrp];
            float uf1 = q[nf * AA + 4  + kgrp] - mb[e * AA + 4  + kgrp];
            float uf2 = q[nf * AA + 8  + kgrp] - mb[e * AA + 8  + kgrp];
            float uf3 = q[nf * AA + 12 + kgrp] - mb[e * AA + 12 + kgrp];

            // ---- coalesced tile load: chunk i*16+hl (row 4i+k, seg s)
            const float4* g4 = (const float4*)(ebase + (size_t)e * 256);
            float4 T0 = g4[ 0 + hl];
            float4 T1 = g4[16 + hl];
            float4 T2 = g4[32 + hl];
            float4 T3 = g4[48 + hl];

            // ---- mb: partial max over own 4-col segment, rows 4i+k
            float p0 = seg_max(T0, ubv);
            float p1 = seg_max(T1, ubv);
            float p2 = seg_max(T2, ubv);
            float p3 = seg_max(T3, ubv);
            // combine across segments (lanes hl^1, hl^2 share k)
            #pragma unroll
            for (int o = 1; o <= 2; o <<= 1) {
                p0 = fmaxf(p0, __shfl_xor_sync(hmask, p0, o, 16));
                p1 = fmaxf(p1, __shfl_xor_sync(hmask, p1, o, 16));
                p2 = fmaxf(p2, __shfl_xor_sync(hmask, p2, o, 16));
                p3 = fmaxf(p3, __shfl_xor_sync(hmask, p3, o, 16));
            }
            // mean over all 16 rows (uniform bitwise across lanes)
            float smb = ((p0 + p1) + (p2 + p3));
            #pragma unroll
            for (int o = 4; o <= 8; o <<= 1)
                smb += __shfl_xor_sync(hmask, smb, o, 16);
            const float mbmean = smb * 0.0625f;

            // ---- mf: candidates for own 4 cols (at = 4s+j), max over rows 4i+k
            float c0 = fmaxf(fmaxf(fmaf(T0.x, EINV, uf0), fmaf(T1.x, EINV, uf1)),
                             fmaxf(fmaf(T2.x, EINV, uf2), fmaf(T3.x, EINV, uf3)));
            float c1 = fmaxf(fmaxf(fmaf(T0.y, EINV, uf0), fmaf(T1.y, EINV, uf1)),
                             fmaxf(fmaf(T2.y, EINV, uf2), fmaf(T3.y, EINV, uf3)));
            float c2 = fmaxf(fmaxf(fmaf(T0.z, EINV, uf0), fmaf(T1.z, EINV, uf1)),
                             fmaxf(fmaf(T2.z, EINV, uf2), fmaf(T3.z, EINV, uf3)));
            float c3 = fmaxf(fmaxf(fmaf(T0.w, EINV, uf0), fmaf(T1.w, EINV, uf1)),
                             fmaxf(fmaf(T2.w, EINV, uf2), fmaf(T3.w, EINV, uf3)));
            // combine across row-groups (lanes hl^4, hl^8 share s)
            #pragma unroll
            for (int o = 4; o <= 8; o <<= 1) {
                c0 = fmaxf(c0, __shfl_xor_sync(hmask, c0, o, 16));
                c1 = fmaxf(c1, __shfl_xor_sync(hmask, c1, o, 16));
                c2 = fmaxf(c2, __shfl_xor_sync(hmask, c2, o, 16));
                c3 = fmaxf(c3, __shfl_xor_sync(hmask, c3, o, 16));
            }
            // mean over all 16 cols (uniform bitwise across lanes)
            float smf = ((c0 + c1) + (c2 + c3));
            #pragma unroll
            for (int o = 1; o <= 2; o <<= 1)
                smf += __shfl_xor_sync(hmask, smf, o, 16);
            const float mfmean = smf * 0.0625f;

            // ---- stores: lane hl writes index 4s+k for both directions.
            // (shuffles above ordered every lane's old-state loads before these)
            const float pv = (sseg == 0) ? p0 : (sseg == 1) ? p1 : (sseg == 2) ? p2 : p3;
            const float cv = (kgrp == 0) ? c0 : (kgrp == 1) ? c1 : (kgrp == 2) ? c2 : c3;
            mb[e * AA + 4 * sseg + kgrp] = pv - mbmean;   // row 4s+k
            mf[e * AA + 4 * sseg + kgrp] = cv - mfmean;   // col 4s+k
        }
        __syncthreads();

        // Phase 2: q = q0 + scatter(mf over edges_to) + scatter(mb over edges_from)
        // per node in ascending-edge order, then per-node argmax.
        for (int n = halfid; n < NN; n += 32) {
            float acc = q0[n * AA + hl];
            int o0 = g_to_off[n], o1 = g_to_off[n + 1];
            for (int i = o0; i < o1; i++) acc += mf[g_to_lst[i] * AA + hl];
            o0 = g_from_off[n]; o1 = g_from_off[n + 1];
            for (int i = o0; i < o1; i++) acc += mb[g_from_lst[i] * AA + hl];
            q[n * AA + hl] = acc;
            float bv = acc; int bi = hl;
            #pragma unroll
            for (int o = 8; o; o >>= 1) {
                float ov = __shfl_xor_sync(hmask, bv, o, 16);
                int   oi = __shfl_xor_sync(hmask, bi, o, 16);
                if (ov > bv || (ov == bv && oi < bi)) { bv = ov; bi = oi; }
            }
            if (hl == 0) a_cur[n] = bi;
        }
        __syncthreads();

        // Phase 3: evaluate greedy action, keep best
        do_eval(false);
    }

    // ---- output: concat(q_max[B], float(a_max[B,N]))
    if (tid == 0) out[b] = *qmax_s;
    if (tid < NN) out[BB + (size_t)b * NN + tid] = (float)a_best[tid];
}

extern "C" void kernel_launch(void* const* d_in, const int* in_sizes, int n_in,
                              void* d_out, int out_size)
{
    const float* nodev = (const float*)d_in[0];   // (B,N,A) f32
    const float* edgev = (const float*)d_in[1];   // (B,E,A,A) f32
    const int*   ef    = (const int*)d_in[2];     // (E,) i32
    const int*   et    = (const int*)d_in[3];     // (E,) i32
    float* out = (float*)d_out;

    static bool attr_set = false;
    if (!attr_set) {
        cudaFuncSetAttribute(dcg_kernel, cudaFuncAttributeMaxDynamicSharedMemorySize, SMEM_BYTES);
        attr_set = true;
    }

    build_adj_kernel<<<1, 64>>>(ef, et);
    dcg_kernel<<<BB, TPB, SMEM_BYTES>>>(nodev, edgev, ef, et, out);
}

// round 12
// speedup vs baseline: 1.6013x; 1.6013x over previous
#include <cuda_runtime.h>
#include <math.h>
#include <stdint.h>

// Problem constants
#define BB 512
#define NN 64
#define EE 512
#define AA 16
#define ITERS 8
#define TPB 512          // threads per CTA (one CTA per batch)
#define EINV (1.0f / 512.0f)

// Adjacency (CSR, ascending edge order) -- built once per launch on device.
__device__ int g_to_off[NN + 1], g_from_off[NN + 1];
__device__ int g_to_lst[EE], g_from_lst[EE];

__global__ void build_adj_kernel(const int* __restrict__ ef, const int* __restrict__ et) {
    __shared__ int sf[EE], st[EE];
    __shared__ int cto[NN], cfr[NN];
    int t = threadIdx.x;
    for (int e = t; e < EE; e += blockDim.x) { sf[e] = ef[e]; st[e] = et[e]; }
    __syncthreads();
    if (t < NN) {
        int ct = 0, cf = 0;
        for (int e = 0; e < EE; e++) { ct += (st[e] == t); cf += (sf[e] == t); }
        cto[t] = ct; cfr[t] = cf;
    }
    __syncthreads();
    if (t == 0) {
        int a = 0, b = 0;
        for (int n = 0; n < NN; n++) {
            g_to_off[n] = a; a += cto[n];
            g_from_off[n] = b; b += cfr[n];
        }
        g_to_off[NN] = a; g_from_off[NN] = b;
    }
    __syncthreads();
    if (t < NN) {
        int ot = g_to_off[t], of = g_from_off[t];
        for (int e = 0; e < EE; e++) {
            if (st[e] == t) g_to_lst[ot++] = e;
            if (sf[e] == t) g_from_lst[of++] = e;
        }
    }
}

// SMEM layout (floats):
//  q0:1024  q:1024  mf:8192  mb:8192
//  red:16 red_node:2 qmax:1  ints: a_cur:64 a_best:64 flag:1 ef:512 et:512
#define SMEM_WORDS (1024 + 1024 + 8192 + 8192 + 16 + 2 + 1 + 64 + 64 + 1 + 512 + 512)
#define SMEM_BYTES (SMEM_WORDS * 4)    // ~76.6KB -> 2 CTAs per SM

__device__ __forceinline__ float4 f4_sub(float4 a, float4 b) {
    float4 r;
    r.x = a.x - b.x; r.y = a.y - b.y; r.z = a.z - b.z; r.w = a.w - b.w;
    return r;
}
// max over 4 elements of (T*EINV + u[j])  -- exact: T*EINV product exact,
// single rounding per add, fmax exactly associative.
__device__ __forceinline__ float seg_max(float4 T, float4 u) {
    float a = fmaxf(fmaf(T.x, EINV, u.x), fmaf(T.y, EINV, u.y));
    float b = fmaxf(fmaf(T.z, EINV, u.z), fmaf(T.w, EINV, u.w));
    return fmaxf(a, b);
}

__global__ __launch_bounds__(TPB, 2)
void dcg_kernel(const float* __restrict__ nodev, const float* __restrict__ edgev,
                const int* __restrict__ ef, const int* __restrict__ et,
                float* __restrict__ out)
{
    extern __shared__ float smem[];
    float* q0      = smem;                        // 1024
    float* q       = q0 + 1024;                   // 1024
    float* mf      = q + 1024;                    // 8192
    float* mb      = mf + 8192;                   // 8192
    float* red     = mb + 8192;                   // 16
    float* red_node = red + 16;                   // 2
    float* qmax_s  = red_node + 2;                // 1
    int* a_cur  = (int*)(qmax_s + 1);             // 64
    int* a_best = a_cur + 64;                     // 64
    int* flag   = a_best + 64;                    // 1
    int* ef_s   = flag + 1;                       // 512
    int* et_s   = ef_s + EE;                      // 512

    const int tid    = threadIdx.x;
    const int b      = blockIdx.x;
    const int halfid = tid >> 4;        // 0..31 half-warp id
    const int hl     = tid & 15;        // lane within half-warp
    const int sseg   = hl & 3;          // column segment s (cols 4s..4s+3)
    const int kgrp   = hl >> 2;         // row-group k (rows 4i+k)
    const unsigned hmask = 0xFFFFu << ((halfid & 1) * 16);
    const int warp = tid >> 5;
    const int lane = tid & 31;
    // reduce-scatter final index permutation: perm[x] = [0,2,1,3][x]
    const int permS = ((sseg & 1) << 1) | (sseg >> 1);
    const int permK = ((kgrp & 1) << 1) | (kgrp >> 1);

    const float* nb    = nodev + (size_t)b * NN * AA;
    const float* ebase = edgev + (size_t)b * EE * AA * AA;

    // ---- init
    for (int i = tid; i < NN * AA; i += TPB) {
        float v = nb[i] * 0.015625f;   // /64 exact
        q0[i] = v; q[i] = v;
    }
    for (int i = tid; i < EE * AA; i += TPB) { mf[i] = 0.f; mb[i] = 0.f; }
    for (int i = tid; i < EE; i += TPB) { ef_s[i] = ef[i]; et_s[i] = et[i]; }
    __syncthreads();

    // ---- argmax of q-array per node (lowest index wins ties, like jnp.argmax)
    auto do_argmax = [&](const float* qa) {
        for (int n = halfid; n < NN; n += 32) {
            float bv = qa[n * AA + hl]; int bi = hl;
            #pragma unroll
            for (int o = 8; o; o >>= 1) {
                float ov = __shfl_xor_sync(hmask, bv, o, 16);
                int   oi = __shfl_xor_sync(hmask, bi, o, 16);
                if (ov > bv || (ov == bv && oi < bi)) { bv = ov; bi = oi; }
            }
            if (hl == 0) a_cur[n] = bi;
        }
    };

    // ---- evaluate action a_cur, update (q_max, a_best). Caller syncs before.
    auto do_eval = [&](bool first) {
        float ev;
        {
            int e  = tid;
            int af = a_cur[ef_s[e]];
            int at = a_cur[et_s[e]];
            ev = ebase[(size_t)e * 256 + af * 16 + at];
        }
        #pragma unroll
        for (int o = 16; o; o >>= 1) ev += __shfl_xor_sync(0xffffffffu, ev, o, 32);
        if (lane == 0) red[warp] = ev;
        if (tid < NN) {
            float nv = q0[tid * AA + a_cur[tid]] * 64.0f;   // node_vals exact
            #pragma unroll
            for (int o = 16; o; o >>= 1) nv += __shfl_xor_sync(0xffffffffu, nv, o, 32);
            if (lane == 0) red_node[warp] = nv;
        }
        __syncthreads();
        if (tid == 0) {
            float es = 0.f;
            #pragma unroll
            for (int w = 0; w < 16; w++) es += red[w];
            float ns = red_node[0] + red_node[1];
            float qv = ns * (1.0f / 64.0f) + es * (1.0f / 512.0f);
            if (first || qv > *qmax_s) { *qmax_s = qv; *flag = 1; }
            else *flag = 0;
        }
        __syncthreads();
        if (*flag && tid < NN) a_best[tid] = a_cur[tid];
        __syncthreads();
    };

    // ---- initial: a_max = argmax(node_vals), q_max = eval
    do_argmax(q0);
    __syncthreads();
    do_eval(true);

    // ---- message-passing iterations
    for (int it = 0; it < ITERS; it++) {
        // Phase 1: one edge per half-warp per pass. Coalesced chunk-ownership:
        // instr i loads chunk i*16+hl -> lane hl holds rows {4i+kgrp}, cols
        // [4s..4s+3]. mb/mf finalized via 2-round reduce-scatters (each lane
        // ends with exactly one element of each message). Max trees: exact
        // fmax reassociations (bitwise == reference). Means: butterfly with
        // lane-offset order chosen so the VALUE-index association tree equals
        // the proven R8 tree (value bits summed in order 3,2,1,0) -- trajectory
        // is bitwise identical to the passing R8 kernel.
        for (int pass = 0; pass < 16; ++pass) {
            const int e = halfid + 32 * pass;
            const int nf = ef_s[e], nt = et_s[e];

            // ---- hoisted loads of ALL old state (before any store this pass)
            const float4 qnt4 = *(const float4*)(q  + nt * AA + 4 * sseg);
            const float4 mfo4 = *(const float4*)(mf + e  * AA + 4 * sseg);
            const float4 ubv  = f4_sub(qnt4, mfo4);      // ub[4s..4s+3]
            // uf scalars for rows 4i+kgrp:
            const float uf0 = q[nf * AA + 0  + kgrp] - mb[e * AA + 0  + kgrp];
            const float uf1 = q[nf * AA + 4  + kgrp] - mb[e * AA + 4  + kgrp];
            const float uf2 = q[nf * AA + 8  + kgrp] - mb[e * AA + 8  + kgrp];
            const float uf3 = q[nf * AA + 12 + kgrp] - mb[e * AA + 12 + kgrp];

            // ---- coalesced tile load
            const float4* g4 = (const float4*)(ebase + (size_t)e * 256);
            const float4 T0 = g4[ 0 + hl];   // row 0+kgrp, seg sseg
            const float4 T1 = g4[16 + hl];   // row 4+kgrp
            const float4 T2 = g4[32 + hl];   // row 8+kgrp
            const float4 T3 = g4[48 + hl];   // row 12+kgrp

            // ---- mb partials: p_i = row (4i+kgrp) max over own 4-col segment
            float p0 = seg_max(T0, ubv);
            float p1 = seg_max(T1, ubv);
            float p2 = seg_max(T2, ubv);
            float p3 = seg_max(T3, ubv);
            // reduce-scatter over s (xor 1 then 2); lane ends with row 4*permS+kgrp
            float mbv;
            {
                const bool s0 = (sseg & 1) != 0;
                float send0 = s0 ? p0 : p2, send1 = s0 ? p1 : p3;
                float keep0 = s0 ? p2 : p0, keep1 = s0 ? p3 : p1;
                float r0 = __shfl_xor_sync(hmask, send0, 1, 16);
                float r1 = __shfl_xor_sync(hmask, send1, 1, 16);
                float a0 = fmaxf(keep0, r0), a1 = fmaxf(keep1, r1);
                const bool s1 = (sseg & 2) != 0;
                float send = s1 ? a0 : a1, keep = s1 ? a1 : a0;
                float r = __shfl_xor_sync(hmask, send, 2, 16);
                mbv = fmaxf(keep, r);
            }

            // ---- mf candidates: C[j] = max over own rows of (T*EINV + uf_i), col 4s+j
            float cx = fmaxf(fmaxf(fmaf(T0.x, EINV, uf0), fmaf(T1.x, EINV, uf1)),
                             fmaxf(fmaf(T2.x, EINV, uf2), fmaf(T3.x, EINV, uf3)));
            float cy = fmaxf(fmaxf(fmaf(T0.y, EINV, uf0), fmaf(T1.y, EINV, uf1)),
                             fmaxf(fmaf(T2.y, EINV, uf2), fmaf(T3.y, EINV, uf3)));
            float cz = fmaxf(fmaxf(fmaf(T0.z, EINV, uf0), fmaf(T1.z, EINV, uf1)),
                             fmaxf(fmaf(T2.z, EINV, uf2), fmaf(T3.z, EINV, uf3)));
            float cw = fmaxf(fmaxf(fmaf(T0.w, EINV, uf0), fmaf(T1.w, EINV, uf1)),
                             fmaxf(fmaf(T2.w, EINV, uf2), fmaf(T3.w, EINV, uf3)));
            // reduce-scatter over k (xor 4 then 8); lane ends with col 4*sseg+permK
            float mfv;
            {
                const bool k0 = (kgrp & 1) != 0;
                float send0 = k0 ? cx : cz, send1 = k0 ? cy : cw;
                float keep0 = k0 ? cz : cx, keep1 = k0 ? cw : cy;
                float r0 = __shfl_xor_sync(hmask, send0, 4, 16);
                float r1 = __shfl_xor_sync(hmask, send1, 4, 16);
                float a0 = fmaxf(keep0, r0), a1 = fmaxf(keep1, r1);
                const bool k1 = (kgrp & 2) != 0;
                float send = k1 ? a0 : a1, keep = k1 ? a1 : a0;
                float r = __shfl_xor_sync(hmask, send, 8, 16);
                mfv = fmaxf(keep, r);
            }

            // ---- means with R8's exact association tree.
            // mb scatter: value(row) bits (v0,v1,v2,v3) = (k0,k1,s1,s0);
            //   flipping value bits in order 3,2,1,0 => lane offsets 1,2,8,4.
            float smb = mbv;
            smb += __shfl_xor_sync(hmask, smb, 1, 16);
            smb += __shfl_xor_sync(hmask, smb, 2, 16);
            smb += __shfl_xor_sync(hmask, smb, 8, 16);
            smb += __shfl_xor_sync(hmask, smb, 4, 16);
            // mf scatter: value(col) bits (c0,c1,c2,c3) = (k1,k0,s0,s1);
            //   flipping value bits in order 3,2,1,0 => lane offsets 2,1,4,8.
            float smf = mfv;
            smf += __shfl_xor_sync(hmask, smf, 2, 16);
            smf += __shfl_xor_sync(hmask, smf, 1, 16);
            smf += __shfl_xor_sync(hmask, smf, 4, 16);
            smf += __shfl_xor_sync(hmask, smf, 8, 16);

            // ---- stores (bijective; butterflies above ordered all lanes' old-
            // state loads before these writes)
            mb[e * AA + 4 * permS + kgrp] = mbv - smb * 0.0625f;
            mf[e * AA + 4 * sseg + permK] = mfv - smf * 0.0625f;
        }
        __syncthreads();

        // Phase 2: q = q0 + scatter(mf over edges_to) + scatter(mb over edges_from)
        // per node in ascending-edge order, then per-node argmax.
        for (int n = halfid; n < NN; n += 32) {
            float acc = q0[n * AA + hl];
            int o0 = g_to_off[n], o1 = g_to_off[n + 1];
            for (int i = o0; i < o1; i++) acc += mf[g_to_lst[i] * AA + hl];
            o0 = g_from_off[n]; o1 = g_from_off[n + 1];
            for (int i = o0; i < o1; i++) acc += mb[g_from_lst[i] * AA + hl];
            q[n * AA + hl] = acc;
            float bv = acc; int bi = hl;
            #pragma unroll
            for (int o = 8; o; o >>= 1) {
                float ov = __shfl_xor_sync(hmask, bv, o, 16);
                int   oi = __shfl_xor_sync(hmask, bi, o, 16);
                if (ov > bv || (ov == bv && oi < bi)) { bv = ov; bi = oi; }
            }
            if (hl == 0) a_cur[n] = bi;
        }
        __syncthreads();

        // Phase 3: evaluate greedy action, keep best
        do_eval(false);
    }

    // ---- output: concat(q_max[B], float(a_max[B,N]))
    if (tid == 0) out[b] = *qmax_s;
    if (tid < NN) out[BB + (size_t)b * NN + tid] = (float)a_best[tid];
}

extern "C" void kernel_launch(void* const* d_in, const int* in_sizes, int n_in,
                              void* d_out, int out_size)
{
    const float* nodev = (const float*)d_in[0];   // (B,N,A) f32
    const float* edgev = (const float*)d_in[1];   // (B,E,A,A) f32
    const int*   ef    = (const int*)d_in[2];     // (E,) i32
    const int*   et    = (const int*)d_in[3];     // (E,) i32
    float* out = (float*)d_out;

    static bool attr_set = false;
    if (!attr_set) {
        cudaFuncSetAttribute(dcg_kernel, cudaFuncAttributeMaxDynamicSharedMemorySize, SMEM_BYTES);
        attr_set = true;
    }

    build_adj_kernel<<<1, 64>>>(ef, et);
    dcg_kernel<<<BB, TPB, SMEM_BYTES>>>(nodev, edgev, ef, et, out);
}